// round 3
// baseline (speedup 1.0000x reference)
#include <cuda_runtime.h>
#include <cuda_bf16.h>

// Fused separable 21-tap Gaussian blur, reflect padding.
// R2: conflict-free smem layouts + packed fma.rn.f32x2 (FFMA2) arithmetic.
//
// Tile 128(x) x 64(y), 256 threads, 2 CTAs/SM.
// raw[84][148]    : input tile (+halo), float4-loadable, LDS.128 conflict-free
//                   with row-major-per-warp task mapping (20*r mod 32, period 8).
// htmp_t[128][86] : horizontal result, TRANSPOSED (col-major) so Phase-B stores
//                   index by row per lane (conflict-free) and Phase-C reads are
//                   contiguous float2 (lane stride 86 words -> disjoint banks).
// u2[21]          : packed {u[j],u[j]} taps in smem, broadcast LDS.64.

#define IMG 1024
#define TX 128
#define TY 64
#define R 10
#define KW 21
#define RAW_W 148
#define RAW_H 84
#define RAW_ELEMS (RAW_H * RAW_W)          // 12432
#define HT_STRIDE 86                       // RAW_H + 2 pad (even: float2 align)
#define HT_ELEMS (TX * HT_STRIDE)          // 11008
#define U2_FOFF (RAW_ELEMS + HT_ELEMS)     // float offset of u2 (byte 93760, 8B aligned)
#define SMEM_BYTES ((RAW_ELEMS + HT_ELEMS + 2 * KW) * 4)   // 93928

typedef unsigned long long ull;

__device__ __forceinline__ ull pk(float lo, float hi) {
    ull r; asm("mov.b64 %0, {%1,%2};" : "=l"(r) : "f"(lo), "f"(hi)); return r;
}
__device__ __forceinline__ void upk(ull v, float& lo, float& hi) {
    asm("mov.b64 {%0,%1}, %2;" : "=f"(lo), "=f"(hi) : "l"(v));
}
__device__ __forceinline__ ull fma2(ull a, ull b, ull c) {
    ull d; asm("fma.rn.f32x2 %0, %1, %2, %3;" : "=l"(d) : "l"(a), "l"(b), "l"(c)); return d;
}
__device__ __forceinline__ ull mul2(ull a, ull b) {
    ull d; asm("mul.rn.f32x2 %0, %1, %2;" : "=l"(d) : "l"(a), "l"(b)); return d;
}

__device__ __forceinline__ int reflect_idx(int i) {
    i = (i < 0) ? -i : i;
    i = (i > IMG - 1) ? (2 * (IMG - 1) - i) : i;
    return i;
}

__global__ void __launch_bounds__(256, 2)
gauss21_kernel(const float* __restrict__ x, const float* __restrict__ k2d,
               float* __restrict__ out) {
    extern __shared__ float sm[];
    float* raw  = sm;                        // [RAW_H][RAW_W]
    float* htmp = sm + RAW_ELEMS;            // [TX][HT_STRIDE] (transposed)
    ull*   usm  = (ull*)(sm + U2_FOFF);      // [KW] packed taps

    const int tid = threadIdx.x;
    const int x0 = blockIdx.x * TX;
    const int y0 = blockIdx.y * TY;
    const long b = blockIdx.z;
    const float* __restrict__ xb = x + b * (long)(IMG * IMG);
    float* __restrict__ ob = out + b * (long)(IMG * IMG);

    // Separable factor: u[j] = k2d[10][j] / sqrt(k2d[10][10]); packed {u,u}.
    if (tid < KW) {
        const float u = __ldg(&k2d[210 + tid]) * rsqrtf(__ldg(&k2d[220]));
        usm[tid] = pk(u, u);
    }

    // ---- Phase A: load input region with reflect indexing (coalesced) ----
    for (int idx = tid; idx < RAW_ELEMS; idx += 256) {
        const int r = idx / RAW_W;
        const int c = idx - r * RAW_W;
        const int gy = reflect_idx(y0 - R + r);
        const int gx = reflect_idx(x0 - R + c);
        raw[idx] = __ldg(&xb[gy * IMG + gx]);
    }
    __syncthreads();

    // ---- Phase B: horizontal conv -> htmp_t. 84 rows x 8 segs, row-major in warp ----
    for (int t = tid; t < RAW_H * 8; t += 256) {
        const int row = t % RAW_H;
        const int seg = t / RAW_H;                       // 0..7
        const float4* rp = (const float4*)(raw + row * RAW_W + seg * 16);

        float w[36];
#pragma unroll
        for (int i = 0; i < 9; i++) {
            const float4 q = rp[i];
            w[4 * i + 0] = q.x; w[4 * i + 1] = q.y;
            w[4 * i + 2] = q.z; w[4 * i + 3] = q.w;
        }
        ull we[18], wo[17];
#pragma unroll
        for (int k = 0; k < 18; k++) we[k] = pk(w[2 * k], w[2 * k + 1]);
#pragma unroll
        for (int k = 0; k < 17; k++) wo[k] = pk(w[2 * k + 1], w[2 * k + 2]);

        ull acc[8];
        {
            const ull u2 = usm[0];
#pragma unroll
            for (int p = 0; p < 8; p++) acc[p] = mul2(u2, we[p]);   // offset 2p (even)
        }
#pragma unroll
        for (int j = 1; j < KW; j++) {
            const ull u2 = usm[j];
#pragma unroll
            for (int p = 0; p < 8; p++) {
                const int o = 2 * p + j;
                acc[p] = fma2(((o & 1) ? wo[(o - 1) / 2] : we[o / 2]), u2, acc[p]);
            }
        }

        float* ht = htmp + row;
#pragma unroll
        for (int p = 0; p < 8; p++) {
            float lo, hi; upk(acc[p], lo, hi);
            ht[(seg * 16 + 2 * p) * HT_STRIDE]     = lo;
            ht[(seg * 16 + 2 * p + 1) * HT_STRIDE] = hi;
        }
    }
    __syncthreads();

    // ---- Phase C: vertical conv from htmp_t -> global. 128 cols x 4 row-blocks ----
#pragma unroll
    for (int it = 0; it < 2; it++) {
        const int t = tid + it * 256;
        const int col = t & (TX - 1);
        const int rb  = (t >> 7) << 4;                   // 0,16,32,48

        const float2* vp = (const float2*)(htmp + col * HT_STRIDE + rb);
        float2 v2[18];
#pragma unroll
        for (int i = 0; i < 18; i++) v2[i] = vp[i];      // v[rb .. rb+35]

        ull ve[18], vo[17];
#pragma unroll
        for (int k = 0; k < 18; k++) ve[k] = pk(v2[k].x, v2[k].y);
#pragma unroll
        for (int k = 0; k < 17; k++) vo[k] = pk(v2[k].y, v2[k + 1].x);

        ull acc[8];
        {
            const ull u2 = usm[0];
#pragma unroll
            for (int p = 0; p < 8; p++) acc[p] = mul2(u2, ve[p]);
        }
#pragma unroll
        for (int j = 1; j < KW; j++) {
            const ull u2 = usm[j];
#pragma unroll
            for (int p = 0; p < 8; p++) {
                const int o = 2 * p + j;
                acc[p] = fma2(((o & 1) ? vo[(o - 1) / 2] : ve[o / 2]), u2, acc[p]);
            }
        }

        float* op = ob + (long)(y0 + rb) * IMG + x0 + col;
#pragma unroll
        for (int p = 0; p < 8; p++) {
            float lo, hi; upk(acc[p], lo, hi);
            op[(long)(2 * p) * IMG]     = lo;
            op[(long)(2 * p + 1) * IMG] = hi;
        }
    }
}

extern "C" void kernel_launch(void* const* d_in, const int* in_sizes, int n_in,
                              void* d_out, int out_size) {
    const float* x   = (const float*)d_in[0];
    const float* k2d = (const float*)d_in[1];
    float* out = (float*)d_out;

    cudaFuncSetAttribute(gauss21_kernel,
                         cudaFuncAttributeMaxDynamicSharedMemorySize, SMEM_BYTES);

    dim3 grid(IMG / TX, IMG / TY, 32);
    dim3 block(256);
    gauss21_kernel<<<grid, block, SMEM_BYTES>>>(x, k2d, out);
}